// round 1
// baseline (speedup 1.0000x reference)
#include <cuda_runtime.h>

#define N_NODES 50000
#define N_EDGES 600000
#define N_GRAPHS 64
#define HID 128
#define EMB 64
#define BN_EPS 1e-5f

// ------------------------- scratch (device globals; no allocs) -------------
__device__ float g_deg[N_NODES];
__device__ float g_dinv[N_NODES];
__device__ float g_hw [N_NODES * HID];   // (h @ W) * dinv[i]
__device__ float g_agg[N_NODES * HID];   // aggregation buffer (self-loop preloaded)
__device__ float g_h  [N_NODES * HID];   // layer activation
__device__ float g_sums[N_GRAPHS * HID];
__device__ float g_cnt [N_GRAPHS];

__device__ __forceinline__ void red4(float* p, float4 v) {
    asm volatile("red.global.add.v4.f32 [%0], {%1,%2,%3,%4};"
                 :: "l"(p), "f"(v.x), "f"(v.y), "f"(v.z), "f"(v.w)
                 : "memory");
}

// ------------------------- setup kernels -----------------------------------
__global__ void init_kernel() {
    int i = blockIdx.x * blockDim.x + threadIdx.x;
    if (i < N_NODES) g_deg[i] = 1.0f;               // self loop
    if (i < N_GRAPHS * HID) g_sums[i] = 0.0f;
}

__global__ void deg_kernel(const int* __restrict__ dst) {
    int e = blockIdx.x * blockDim.x + threadIdx.x;
    if (e < N_EDGES) atomicAdd(&g_deg[dst[e]], 1.0f);
}

__global__ void dinv_kernel() {
    int i = blockIdx.x * blockDim.x + threadIdx.x;
    if (i < N_NODES) g_dinv[i] = rsqrtf(g_deg[i]);
}

// batch is sorted -> per-graph node count by binary search (no atomics)
__global__ void cnt_kernel(const int* __restrict__ batch) {
    int g = threadIdx.x;
    if (g >= N_GRAPHS) return;
    int lo0 = 0, hi0 = N_NODES;       // lower_bound(g)
    while (lo0 < hi0) { int m = (lo0 + hi0) >> 1; if (batch[m] <  g) lo0 = m + 1; else hi0 = m; }
    int lo1 = lo0, hi1 = N_NODES;     // lower_bound(g+1)
    while (lo1 < hi1) { int m = (lo1 + hi1) >> 1; if (batch[m] <= g) lo1 = m + 1; else hi1 = m; }
    g_cnt[g] = (float)(lo1 - lo0);
}

// ------------------------- layer-1 GEMM (K=5) -------------------------------
// hw2 = (x @ W1) * dinv ; also agg = hw2 (self-loop init)
__global__ void gemm_in_kernel(const float* __restrict__ x, const float* __restrict__ W1) {
    int col = threadIdx.x;                           // 128 threads = 128 cols
    float w0 = W1[0 * HID + col], w1 = W1[1 * HID + col], w2 = W1[2 * HID + col],
          w3 = W1[3 * HID + col], w4 = W1[4 * HID + col];
    int base = blockIdx.x * 32;
    #pragma unroll 4
    for (int r = 0; r < 32; r++) {
        int i = base + r;
        if (i >= N_NODES) return;
        float x0 = __ldg(x + i * 5 + 0), x1 = __ldg(x + i * 5 + 1), x2 = __ldg(x + i * 5 + 2),
              x3 = __ldg(x + i * 5 + 3), x4 = __ldg(x + i * 5 + 4);
        float acc = x0 * w0 + x1 * w1 + x2 * w2 + x3 * w3 + x4 * w4;
        acc *= g_dinv[i];
        g_hw [i * HID + col] = acc;
        g_agg[i * HID + col] = acc;
    }
}

// ------------------------- 128x128 GEMM (layers 2/3) ------------------------
// A = g_h (N x 128), W (128 x 128). Writes g_hw = g_agg = (A@W)*dinv.
// BM=128 rows/block, full K and N. 256 threads: warp w owns rows w*16..+15,
// lane l owns cols l*4..+3. A-loads are warp-broadcast (same address).
__global__ void __launch_bounds__(256, 1)
gemm128_kernel(const float* __restrict__ W) {
    extern __shared__ float smem[];
    float* As = smem;                 // 128*128 (h tile, row-major)
    float* Bs = smem + HID * HID;     // 128*128 (W)
    float4* As4 = (float4*)As;
    float4* Bs4 = (float4*)Bs;
    const float4* W4 = (const float4*)W;

    int i0 = blockIdx.x * 128;
    int t  = threadIdx.x;

    #pragma unroll
    for (int it = 0; it < 16; it++) {
        int idx = it * 256 + t;
        Bs4[idx] = W4[idx];
        int row = idx >> 5;
        int gi  = i0 + row;
        float4 v = make_float4(0.f, 0.f, 0.f, 0.f);
        if (gi < N_NODES) v = *(const float4*)(g_h + gi * HID + (idx & 31) * 4);
        As4[idx] = v;
    }
    __syncthreads();

    int w = t >> 5, l = t & 31;
    float acc[16][4];
    #pragma unroll
    for (int r = 0; r < 16; r++) { acc[r][0] = acc[r][1] = acc[r][2] = acc[r][3] = 0.f; }

    const float* Arow = As + (w * 16) * HID;
    #pragma unroll 2
    for (int k = 0; k < HID; k++) {
        float4 b = Bs4[k * 32 + l];
        #pragma unroll
        for (int r = 0; r < 16; r++) {
            float a = Arow[r * HID + k];
            acc[r][0] += a * b.x; acc[r][1] += a * b.y;
            acc[r][2] += a * b.z; acc[r][3] += a * b.w;
        }
    }

    #pragma unroll
    for (int r = 0; r < 16; r++) {
        int gi = i0 + w * 16 + r;
        if (gi < N_NODES) {
            float s = g_dinv[gi];
            float4 v = make_float4(acc[r][0] * s, acc[r][1] * s, acc[r][2] * s, acc[r][3] * s);
            *(float4*)(g_hw  + gi * HID + l * 4) = v;
            *(float4*)(g_agg + gi * HID + l * 4) = v;
        }
    }
}

// ------------------------- edge scatter -------------------------------------
// agg[dst] += hw2[src]   (one warp per edge, float4 vector reductions)
__global__ void scatter_kernel(const int* __restrict__ src, const int* __restrict__ dst) {
    int gid = blockIdx.x * blockDim.x + threadIdx.x;
    int e = gid >> 5;
    if (e >= N_EDGES) return;
    int lane = gid & 31;
    int s = __ldg(src + e);
    int d = __ldg(dst + e);
    float4 v = *(const float4*)(g_hw + s * HID + lane * 4);
    red4(g_agg + d * HID + lane * 4, v);
}

// ------------------------- bn + relu ----------------------------------------
__global__ void bnrelu_kernel(const float* __restrict__ b, const float* __restrict__ gm,
                              const float* __restrict__ be) {
    int tid = blockIdx.x * blockDim.x + threadIdx.x;   // over N_NODES*32 float4s
    if (tid >= N_NODES * 32) return;
    int i = tid >> 5, c4 = tid & 31;
    float di = g_dinv[i];
    float rs = rsqrtf(1.0f + BN_EPS);
    float4 a  = *(const float4*)(g_agg + i * HID + c4 * 4);
    float4 bb = __ldg((const float4*)b  + c4);
    float4 gg = __ldg((const float4*)gm + c4);
    float4 ee = __ldg((const float4*)be + c4);
    float4 v;
    v.x = fmaxf((a.x * di + bb.x) * (gg.x * rs) + ee.x, 0.f);
    v.y = fmaxf((a.y * di + bb.y) * (gg.y * rs) + ee.y, 0.f);
    v.z = fmaxf((a.z * di + bb.z) * (gg.z * rs) + ee.z, 0.f);
    v.w = fmaxf((a.w * di + bb.w) * (gg.w * rs) + ee.w, 0.f);
    *(float4*)(g_h + i * HID + c4 * 4) = v;
}

// layer-3 bn+relu fused with mean-pool accumulation (atomic into g_sums)
__global__ void bnrelu_pool_kernel(const float* __restrict__ b, const float* __restrict__ gm,
                                   const float* __restrict__ be, const int* __restrict__ batch) {
    int tid = blockIdx.x * blockDim.x + threadIdx.x;
    if (tid >= N_NODES * 32) return;
    int i = tid >> 5, c4 = tid & 31;
    float di = g_dinv[i];
    float rs = rsqrtf(1.0f + BN_EPS);
    float4 a  = *(const float4*)(g_agg + i * HID + c4 * 4);
    float4 bb = __ldg((const float4*)b  + c4);
    float4 gg = __ldg((const float4*)gm + c4);
    float4 ee = __ldg((const float4*)be + c4);
    float4 v;
    v.x = fmaxf((a.x * di + bb.x) * (gg.x * rs) + ee.x, 0.f);
    v.y = fmaxf((a.y * di + bb.y) * (gg.y * rs) + ee.y, 0.f);
    v.z = fmaxf((a.z * di + bb.z) * (gg.z * rs) + ee.z, 0.f);
    v.w = fmaxf((a.w * di + bb.w) * (gg.w * rs) + ee.w, 0.f);
    int g = __ldg(batch + i);
    red4(g_sums + g * HID + c4 * 4, v);
}

// ------------------------- final projection ---------------------------------
// out[g][j] = (sums[g]/max(cnt,1)) @ Wp + bp     grid=64 blocks, 64 threads
__global__ void final_kernel(const float* __restrict__ Wp, const float* __restrict__ bp,
                             float* __restrict__ out) {
    __shared__ float p[HID];
    int g = blockIdx.x, j = threadIdx.x;
    float invc = 1.0f / fmaxf(g_cnt[g], 1.0f);
    for (int c = j; c < HID; c += EMB) p[c] = g_sums[g * HID + c] * invc;
    __syncthreads();
    float acc = __ldg(bp + j);
    #pragma unroll 8
    for (int c = 0; c < HID; c++) acc += p[c] * __ldg(Wp + c * EMB + j);
    out[g * EMB + j] = acc;
}

// ------------------------- launch -------------------------------------------
extern "C" void kernel_launch(void* const* d_in, const int* in_sizes, int n_in,
                              void* d_out, int out_size) {
    const float* x   = (const float*)d_in[0];
    const int*   src = (const int*)  d_in[1];
    const int*   dst = (const int*)  d_in[2];
    const int*   bat = (const int*)  d_in[3];
    const float* W1  = (const float*)d_in[4];
    const float* b1  = (const float*)d_in[5];
    const float* W2  = (const float*)d_in[6];
    const float* b2  = (const float*)d_in[7];
    const float* W3  = (const float*)d_in[8];
    const float* b3  = (const float*)d_in[9];
    const float* g1  = (const float*)d_in[10];
    const float* be1 = (const float*)d_in[11];
    const float* g2  = (const float*)d_in[12];
    const float* be2 = (const float*)d_in[13];
    const float* g3  = (const float*)d_in[14];
    const float* be3 = (const float*)d_in[15];
    const float* Wp  = (const float*)d_in[16];
    const float* bp  = (const float*)d_in[17];
    float* out = (float*)d_out;

    const int SMEM = 2 * HID * HID * (int)sizeof(float);   // 128 KB
    cudaFuncSetAttribute(gemm128_kernel, cudaFuncAttributeMaxDynamicSharedMemorySize, SMEM);

    const int ELT_BLOCKS  = (N_NODES * 32 + 255) / 256;
    const int SCAT_BLOCKS = (N_EDGES * 32 + 255) / 256;
    const int GEMM_BLOCKS = (N_NODES + 127) / 128;

    init_kernel<<<(N_NODES + 255) / 256, 256>>>();
    deg_kernel <<<(N_EDGES + 255) / 256, 256>>>(dst);
    dinv_kernel<<<(N_NODES + 255) / 256, 256>>>();
    cnt_kernel <<<1, 64>>>(bat);

    // layer 1
    gemm_in_kernel<<<(N_NODES + 31) / 32, 128>>>(x, W1);
    scatter_kernel<<<SCAT_BLOCKS, 256>>>(src, dst);
    bnrelu_kernel <<<ELT_BLOCKS, 256>>>(b1, g1, be1);

    // layer 2
    gemm128_kernel<<<GEMM_BLOCKS, 256, SMEM>>>(W2);
    scatter_kernel<<<SCAT_BLOCKS, 256>>>(src, dst);
    bnrelu_kernel <<<ELT_BLOCKS, 256>>>(b2, g2, be2);

    // layer 3 (bn+relu fused with pooling)
    gemm128_kernel<<<GEMM_BLOCKS, 256, SMEM>>>(W3);
    scatter_kernel<<<SCAT_BLOCKS, 256>>>(src, dst);
    bnrelu_pool_kernel<<<ELT_BLOCKS, 256>>>(b3, g3, be3, bat);

    final_kernel<<<N_GRAPHS, EMB>>>(Wp, bp, out);
}

// round 2
// speedup vs baseline: 1.5111x; 1.5111x over previous
#include <cuda_runtime.h>

#define N_NODES 50000
#define N_EDGES 600000
#define N_GRAPHS 64
#define HID 128
#define EMB 64
#define BN_EPS 1e-5f
#define NB_SCAN 196            // ceil(50000/256)

// ------------------------- scratch (device globals; no allocs) -------------
__device__ float g_dinv[N_NODES];
__device__ float g_hw [N_NODES * HID];   // (h @ W) * dinv[i]
__device__ float g_h  [N_NODES * HID];   // layer activation
__device__ float g_sums[N_GRAPHS * HID];
__device__ int   g_cnti[N_GRAPHS];
__device__ int   g_rowcnt[N_NODES];
__device__ int   g_rowptr[N_NODES + 1];
__device__ int   g_cursor[N_NODES];
__device__ int   g_col[N_EDGES];
__device__ int   g_bsum[NB_SCAN];
__device__ int   g_boff[NB_SCAN];

__device__ __forceinline__ void red4(float* p, float4 v) {
    asm volatile("red.global.add.v4.f32 [%0], {%1,%2,%3,%4};"
                 :: "l"(p), "f"(v.x), "f"(v.y), "f"(v.z), "f"(v.w)
                 : "memory");
}

// ------------------------- CSR build ---------------------------------------
__global__ void zero_kernel() {
    int i = blockIdx.x * blockDim.x + threadIdx.x;
    if (i < N_NODES) g_rowcnt[i] = 0;
    if (i < N_GRAPHS * HID) g_sums[i] = 0.0f;
    if (i < N_GRAPHS) g_cnti[i] = 0;
    if (i == 0) g_rowptr[N_NODES] = N_EDGES;
}

// histogram over dst + per-graph node counts (batch sorted -> warp-aggregated)
__global__ void hist_kernel(const int* __restrict__ dst, const int* __restrict__ batch) {
    int t = blockIdx.x * blockDim.x + threadIdx.x;
    if (t < N_EDGES) atomicAdd(&g_rowcnt[dst[t]], 1);
    if (t < N_NODES) atomicAdd(&g_cnti[batch[t]], 1);
}

// block partial sums of rowcnt + dinv = rsqrt(indeg + 1)
__global__ void part_kernel() {
    int i = blockIdx.x * 256 + threadIdx.x;
    int c = (i < N_NODES) ? g_rowcnt[i] : 0;
    if (i < N_NODES) g_dinv[i] = rsqrtf((float)(c + 1));
    __shared__ int sm[256];
    sm[threadIdx.x] = c; __syncthreads();
    #pragma unroll
    for (int s = 128; s > 0; s >>= 1) {
        if (threadIdx.x < s) sm[threadIdx.x] += sm[threadIdx.x + s];
        __syncthreads();
    }
    if (threadIdx.x == 0) g_bsum[blockIdx.x] = sm[0];
}

// scan the 196 block sums (1 block)
__global__ void scanb_kernel() {
    int t = threadIdx.x;
    __shared__ int sm[256];
    int v = (t < NB_SCAN) ? g_bsum[t] : 0;
    sm[t] = v; __syncthreads();
    #pragma unroll
    for (int off = 1; off < 256; off <<= 1) {
        int a = (t >= off) ? sm[t - off] : 0;
        __syncthreads();
        sm[t] += a;
        __syncthreads();
    }
    if (t < NB_SCAN) g_boff[t] = sm[t] - v;   // exclusive
}

// per-block scan + base offset -> rowptr, cursor
__global__ void write_kernel() {
    int t = threadIdx.x, b = blockIdx.x;
    int i = b * 256 + t;
    int c = (i < N_NODES) ? g_rowcnt[i] : 0;
    __shared__ int sm[256];
    sm[t] = c; __syncthreads();
    #pragma unroll
    for (int off = 1; off < 256; off <<= 1) {
        int a = (t >= off) ? sm[t - off] : 0;
        __syncthreads();
        sm[t] += a;
        __syncthreads();
    }
    if (i < N_NODES) {
        int excl = sm[t] - c + g_boff[b];
        g_rowptr[i] = excl;
        g_cursor[i] = excl;
    }
}

__global__ void fill_kernel(const int* __restrict__ src, const int* __restrict__ dst) {
    int e = blockIdx.x * blockDim.x + threadIdx.x;
    if (e < N_EDGES) {
        int p = atomicAdd(&g_cursor[dst[e]], 1);
        g_col[p] = src[e];
    }
}

// ------------------------- layer-1 GEMM (K=5) -------------------------------
__global__ void gemm_in_kernel(const float* __restrict__ x, const float* __restrict__ W1) {
    int col = threadIdx.x;
    float w0 = W1[0 * HID + col], w1 = W1[1 * HID + col], w2 = W1[2 * HID + col],
          w3 = W1[3 * HID + col], w4 = W1[4 * HID + col];
    int base = blockIdx.x * 32;
    #pragma unroll 4
    for (int r = 0; r < 32; r++) {
        int i = base + r;
        if (i >= N_NODES) return;
        float x0 = __ldg(x + i * 5 + 0), x1 = __ldg(x + i * 5 + 1), x2 = __ldg(x + i * 5 + 2),
              x3 = __ldg(x + i * 5 + 3), x4 = __ldg(x + i * 5 + 4);
        float acc = (x0 * w0 + x1 * w1 + x2 * w2 + x3 * w3 + x4 * w4) * g_dinv[i];
        g_hw[i * HID + col] = acc;
    }
}

// ------------------------- 128x128 GEMM (layers 2/3) ------------------------
// 512 threads: warp w owns rows w*8..+7, lane l owns cols l*4..+3.
__global__ void __launch_bounds__(512, 1)
gemm128_kernel(const float* __restrict__ W) {
    extern __shared__ float smem[];
    float* As = smem;                 // 128x128 h tile
    float* Bs = smem + HID * HID;     // 128x128 W
    float4* As4 = (float4*)As;
    float4* Bs4 = (float4*)Bs;
    const float4* W4 = (const float4*)W;

    int i0 = blockIdx.x * 128;
    int t  = threadIdx.x;

    #pragma unroll
    for (int it = 0; it < 8; it++) {
        int idx = it * 512 + t;       // 0..4095
        Bs4[idx] = W4[idx];
        int row = idx >> 5;
        int gi  = i0 + row;
        float4 v = make_float4(0.f, 0.f, 0.f, 0.f);
        if (gi < N_NODES) v = *(const float4*)(g_h + gi * HID + (idx & 31) * 4);
        As4[idx] = v;
    }
    __syncthreads();

    int w = t >> 5, l = t & 31;
    float acc[8][4];
    #pragma unroll
    for (int r = 0; r < 8; r++) { acc[r][0] = acc[r][1] = acc[r][2] = acc[r][3] = 0.f; }

    const float* Arow = As + (w * 8) * HID;
    #pragma unroll 4
    for (int k = 0; k < HID; k++) {
        float4 b = Bs4[k * 32 + l];
        #pragma unroll
        for (int r = 0; r < 8; r++) {
            float a = Arow[r * HID + k];
            acc[r][0] += a * b.x; acc[r][1] += a * b.y;
            acc[r][2] += a * b.z; acc[r][3] += a * b.w;
        }
    }

    #pragma unroll
    for (int r = 0; r < 8; r++) {
        int gi = i0 + w * 8 + r;
        if (gi < N_NODES) {
            float s = g_dinv[gi];
            *(float4*)(g_hw + gi * HID + l * 4) =
                make_float4(acc[r][0] * s, acc[r][1] * s, acc[r][2] * s, acc[r][3] * s);
        }
    }
}

// ------------------------- fused gather-aggregate + bn + relu ---------------
// one warp per node; prefetch 32 neighbor indices, shfl-broadcast -> independent gathers
template<bool POOL>
__global__ void __launch_bounds__(256)
agg_kernel(const float* __restrict__ b, const float* __restrict__ gm,
           const float* __restrict__ be, const int* __restrict__ batch) {
    int n = blockIdx.x * 8 + (threadIdx.x >> 5);
    if (n >= N_NODES) return;
    int lane = threadIdx.x & 31;
    const float4* hw4 = (const float4*)g_hw;

    float4 acc = hw4[n * 32 + lane];          // self-loop term (already * dinv[src])
    int start = g_rowptr[n], end = g_rowptr[n + 1];

    for (int base = start; base < end; base += 32) {
        int j = base + lane;
        int idx = (j < end) ? g_col[j] : 0;
        int m = end - base; if (m > 32) m = 32;
        for (int k = 0; k < m; k++) {
            int s = __shfl_sync(0xffffffffu, idx, k);
            float4 v = hw4[s * 32 + lane];
            acc.x += v.x; acc.y += v.y; acc.z += v.z; acc.w += v.w;
        }
    }

    float di = g_dinv[n];
    float rs = rsqrtf(1.0f + BN_EPS);
    float4 bb = __ldg((const float4*)b  + lane);
    float4 gg = __ldg((const float4*)gm + lane);
    float4 ee = __ldg((const float4*)be + lane);
    float4 v;
    v.x = fmaxf((acc.x * di + bb.x) * (gg.x * rs) + ee.x, 0.f);
    v.y = fmaxf((acc.y * di + bb.y) * (gg.y * rs) + ee.y, 0.f);
    v.z = fmaxf((acc.z * di + bb.z) * (gg.z * rs) + ee.z, 0.f);
    v.w = fmaxf((acc.w * di + bb.w) * (gg.w * rs) + ee.w, 0.f);

    if (POOL) {
        int g = __ldg(batch + n);
        red4(g_sums + g * HID + lane * 4, v);
    } else {
        *(float4*)(g_h + n * HID + lane * 4) = v;
    }
}

// ------------------------- final projection ---------------------------------
__global__ void final_kernel(const float* __restrict__ Wp, const float* __restrict__ bp,
                             float* __restrict__ out) {
    __shared__ float p[HID];
    int g = blockIdx.x, j = threadIdx.x;
    float invc = 1.0f / fmaxf((float)g_cnti[g], 1.0f);
    for (int c = j; c < HID; c += EMB) p[c] = g_sums[g * HID + c] * invc;
    __syncthreads();
    float acc = __ldg(bp + j);
    #pragma unroll 8
    for (int c = 0; c < HID; c++) acc += p[c] * __ldg(Wp + c * EMB + j);
    out[g * EMB + j] = acc;
}

// ------------------------- launch -------------------------------------------
extern "C" void kernel_launch(void* const* d_in, const int* in_sizes, int n_in,
                              void* d_out, int out_size) {
    const float* x   = (const float*)d_in[0];
    const int*   src = (const int*)  d_in[1];
    const int*   dst = (const int*)  d_in[2];
    const int*   bat = (const int*)  d_in[3];
    const float* W1  = (const float*)d_in[4];
    const float* b1  = (const float*)d_in[5];
    const float* W2  = (const float*)d_in[6];
    const float* b2  = (const float*)d_in[7];
    const float* W3  = (const float*)d_in[8];
    const float* b3  = (const float*)d_in[9];
    const float* g1  = (const float*)d_in[10];
    const float* be1 = (const float*)d_in[11];
    const float* g2  = (const float*)d_in[12];
    const float* be2 = (const float*)d_in[13];
    const float* g3  = (const float*)d_in[14];
    const float* be3 = (const float*)d_in[15];
    const float* Wp  = (const float*)d_in[16];
    const float* bp  = (const float*)d_in[17];
    float* out = (float*)d_out;

    const int SMEM = 2 * HID * HID * (int)sizeof(float);   // 128 KB
    cudaFuncSetAttribute(gemm128_kernel, cudaFuncAttributeMaxDynamicSharedMemorySize, SMEM);

    const int GEMM_BLOCKS = (N_NODES + 127) / 128;
    const int AGG_BLOCKS  = (N_NODES + 7) / 8;

    // CSR build (per call; deterministic work)
    zero_kernel <<<(N_NODES + 255) / 256, 256>>>();
    hist_kernel <<<(N_EDGES + 255) / 256, 256>>>(dst, bat);
    part_kernel <<<NB_SCAN, 256>>>();
    scanb_kernel<<<1, 256>>>();
    write_kernel<<<NB_SCAN, 256>>>();
    fill_kernel <<<(N_EDGES + 255) / 256, 256>>>(src, dst);

    // layer 1
    gemm_in_kernel<<<(N_NODES + 31) / 32, 128>>>(x, W1);
    agg_kernel<false><<<AGG_BLOCKS, 256>>>(b1, g1, be1, bat);

    // layer 2
    gemm128_kernel<<<GEMM_BLOCKS, 512, SMEM>>>(W2);
    agg_kernel<false><<<AGG_BLOCKS, 256>>>(b2, g2, be2, bat);

    // layer 3 (+ fused mean-pool accumulation)
    gemm128_kernel<<<GEMM_BLOCKS, 512, SMEM>>>(W3);
    agg_kernel<true><<<AGG_BLOCKS, 256>>>(b3, g3, be3, bat);

    final_kernel<<<N_GRAPHS, EMB>>>(Wp, bp, out);
}

// round 4
// speedup vs baseline: 1.5894x; 1.0518x over previous
#include <cuda_runtime.h>

#define N_NODES 50000
#define N_EDGES 600000
#define N_GRAPHS 64
#define HID 128
#define EMB 64
#define BN_EPS 1e-5f
#define NB_SCAN 196            // ceil(50000/256)
#define XS_STRIDE 8            // padded so float4 loads stay 16B-aligned

// ------------------------- scratch (device globals; no allocs) -------------
__device__ float g_dinv[N_NODES];
__device__ float g_xs [N_NODES * XS_STRIDE];  // x * dinv (padded rows)
__device__ float g_hw [N_NODES * HID];   // (h @ W) * dinv[i]
__device__ float g_h  [N_NODES * HID];   // layer activation
__device__ float g_sums[N_GRAPHS * HID];
__device__ int   g_cnti[N_GRAPHS];
__device__ int   g_rowcnt[N_NODES];
__device__ int   g_rowptr[N_NODES + 1];
__device__ int   g_cursor[N_NODES];
__device__ int   g_col[N_EDGES];
__device__ int   g_bsum[NB_SCAN];
__device__ int   g_boff[NB_SCAN];

__device__ __forceinline__ void red4(float* p, float4 v) {
    asm volatile("red.global.add.v4.f32 [%0], {%1,%2,%3,%4};"
                 :: "l"(p), "f"(v.x), "f"(v.y), "f"(v.z), "f"(v.w)
                 : "memory");
}

// ------------------------- CSR build ---------------------------------------
__global__ void zero_kernel() {
    int i = blockIdx.x * blockDim.x + threadIdx.x;
    if (i < N_NODES) g_rowcnt[i] = 0;
    if (i < N_GRAPHS * HID) g_sums[i] = 0.0f;
    if (i < N_GRAPHS) g_cnti[i] = 0;
    if (i == 0) g_rowptr[N_NODES] = N_EDGES;
}

__global__ void hist_kernel(const int* __restrict__ dst, const int* __restrict__ batch) {
    int t = blockIdx.x * blockDim.x + threadIdx.x;
    if (t < N_EDGES) atomicAdd(&g_rowcnt[dst[t]], 1);
    if (t < N_NODES) atomicAdd(&g_cnti[batch[t]], 1);
}

// block partial sums of rowcnt + dinv = rsqrt(indeg+1) + xs = x*dinv
__global__ void part_kernel(const float* __restrict__ x) {
    int i = blockIdx.x * 256 + threadIdx.x;
    int c = (i < N_NODES) ? g_rowcnt[i] : 0;
    if (i < N_NODES) {
        float di = rsqrtf((float)(c + 1));
        g_dinv[i] = di;
        #pragma unroll
        for (int k = 0; k < 5; k++) g_xs[i * XS_STRIDE + k] = __ldg(x + i * 5 + k) * di;
    }
    __shared__ int sm[256];
    sm[threadIdx.x] = c; __syncthreads();
    #pragma unroll
    for (int s = 128; s > 0; s >>= 1) {
        if (threadIdx.x < s) sm[threadIdx.x] += sm[threadIdx.x + s];
        __syncthreads();
    }
    if (threadIdx.x == 0) g_bsum[blockIdx.x] = sm[0];
}

__global__ void scanb_kernel() {
    int t = threadIdx.x;
    __shared__ int sm[256];
    int v = (t < NB_SCAN) ? g_bsum[t] : 0;
    sm[t] = v; __syncthreads();
    #pragma unroll
    for (int off = 1; off < 256; off <<= 1) {
        int a = (t >= off) ? sm[t - off] : 0;
        __syncthreads();
        sm[t] += a;
        __syncthreads();
    }
    if (t < NB_SCAN) g_boff[t] = sm[t] - v;   // exclusive
}

__global__ void write_kernel() {
    int t = threadIdx.x, b = blockIdx.x;
    int i = b * 256 + t;
    int c = (i < N_NODES) ? g_rowcnt[i] : 0;
    __shared__ int sm[256];
    sm[t] = c; __syncthreads();
    #pragma unroll
    for (int off = 1; off < 256; off <<= 1) {
        int a = (t >= off) ? sm[t - off] : 0;
        __syncthreads();
        sm[t] += a;
        __syncthreads();
    }
    if (i < N_NODES) {
        int excl = sm[t] - c + g_boff[b];
        g_rowptr[i] = excl;
        g_cursor[i] = excl;
    }
}

__global__ void fill_kernel(const int* __restrict__ src, const int* __restrict__ dst) {
    int e = blockIdx.x * blockDim.x + threadIdx.x;
    if (e < N_EDGES) {
        int p = atomicAdd(&g_cursor[dst[e]], 1);
        g_col[p] = src[e];
    }
}

// ------------------------- fused layer 1 ------------------------------------
// warp per node: aggregate 5-wide xs over neighbors (lane-parallel), warp-
// allreduce, then each lane computes 4 of 128 output cols (5x128 GEMM) with
// bn+relu epilogue. Writes g_h.
__global__ void __launch_bounds__(256)
layer1_kernel(const float* __restrict__ W1, const float* __restrict__ b1,
              const float* __restrict__ gm, const float* __restrict__ be) {
    int n = blockIdx.x * 8 + (threadIdx.x >> 5);
    if (n >= N_NODES) return;
    int lane = threadIdx.x & 31;

    float a0 = 0.f, a1 = 0.f, a2 = 0.f, a3 = 0.f, a4 = 0.f;
    int start = g_rowptr[n], end = g_rowptr[n + 1];
    for (int j = start + lane; j < end; j += 32) {
        int s = g_col[j];
        float4 v = *(const float4*)(g_xs + s * XS_STRIDE);
        float  w = g_xs[s * XS_STRIDE + 4];
        a0 += v.x; a1 += v.y; a2 += v.z; a3 += v.w; a4 += w;
    }
    #pragma unroll
    for (int off = 16; off > 0; off >>= 1) {
        a0 += __shfl_xor_sync(0xffffffffu, a0, off);
        a1 += __shfl_xor_sync(0xffffffffu, a1, off);
        a2 += __shfl_xor_sync(0xffffffffu, a2, off);
        a3 += __shfl_xor_sync(0xffffffffu, a3, off);
        a4 += __shfl_xor_sync(0xffffffffu, a4, off);
    }
    // self loop
    float4 sv = *(const float4*)(g_xs + n * XS_STRIDE);
    a0 += sv.x; a1 += sv.y; a2 += sv.z; a3 += sv.w; a4 += g_xs[n * XS_STRIDE + 4];

    float di = g_dinv[n];
    float rs = rsqrtf(1.0f + BN_EPS);
    float4 w0 = __ldg((const float4*)(W1 + 0 * HID) + lane);
    float4 w1 = __ldg((const float4*)(W1 + 1 * HID) + lane);
    float4 w2 = __ldg((const float4*)(W1 + 2 * HID) + lane);
    float4 w3 = __ldg((const float4*)(W1 + 3 * HID) + lane);
    float4 w4 = __ldg((const float4*)(W1 + 4 * HID) + lane);
    float4 bb = __ldg((const float4*)b1 + lane);
    float4 gg = __ldg((const float4*)gm + lane);
    float4 ee = __ldg((const float4*)be + lane);

    float4 v;
    v.x = fmaxf(((a0*w0.x + a1*w1.x + a2*w2.x + a3*w3.x + a4*w4.x) * di + bb.x) * (gg.x*rs) + ee.x, 0.f);
    v.y = fmaxf(((a0*w0.y + a1*w1.y + a2*w2.y + a3*w3.y + a4*w4.y) * di + bb.y) * (gg.y*rs) + ee.y, 0.f);
    v.z = fmaxf(((a0*w0.z + a1*w1.z + a2*w2.z + a3*w3.z + a4*w4.z) * di + bb.z) * (gg.z*rs) + ee.z, 0.f);
    v.w = fmaxf(((a0*w0.w + a1*w1.w + a2*w2.w + a3*w3.w + a4*w4.w) * di + bb.w) * (gg.w*rs) + ee.w, 0.f);
    *(float4*)(g_h + n * HID + lane * 4) = v;
}

// ------------------------- 128x128 GEMM (layers 2/3) ------------------------
__global__ void __launch_bounds__(512, 1)
gemm128_kernel(const float* __restrict__ W) {
    extern __shared__ float smem[];
    float* As = smem;                 // 128x128 h tile
    float* Bs = smem + HID * HID;     // 128x128 W
    float4* As4 = (float4*)As;
    float4* Bs4 = (float4*)Bs;
    const float4* W4 = (const float4*)W;

    int i0 = blockIdx.x * 128;
    int t  = threadIdx.x;

    #pragma unroll
    for (int it = 0; it < 8; it++) {
        int idx = it * 512 + t;       // 0..4095
        Bs4[idx] = W4[idx];
        int row = idx >> 5;
        int gi  = i0 + row;
        float4 v = make_float4(0.f, 0.f, 0.f, 0.f);
        if (gi < N_NODES) v = *(const float4*)(g_h + gi * HID + (idx & 31) * 4);
        As4[idx] = v;
    }
    __syncthreads();

    int w = t >> 5, l = t & 31;
    float acc[8][4];
    #pragma unroll
    for (int r = 0; r < 8; r++) { acc[r][0] = acc[r][1] = acc[r][2] = acc[r][3] = 0.f; }

    const float* Arow = As + (w * 8) * HID;
    #pragma unroll 4
    for (int k = 0; k < HID; k++) {
        float4 b = Bs4[k * 32 + l];
        #pragma unroll
        for (int r = 0; r < 8; r++) {
            float a = Arow[r * HID + k];
            acc[r][0] += a * b.x; acc[r][1] += a * b.y;
            acc[r][2] += a * b.z; acc[r][3] += a * b.w;
        }
    }

    #pragma unroll
    for (int r = 0; r < 8; r++) {
        int gi = i0 + w * 8 + r;
        if (gi < N_NODES) {
            float s = g_dinv[gi];
            *(float4*)(g_hw + gi * HID + l * 4) =
                make_float4(acc[r][0] * s, acc[r][1] * s, acc[r][2] * s, acc[r][3] * s);
        }
    }
}

// ------------------------- fused gather-aggregate + bn + relu ---------------
template<bool POOL>
__global__ void __launch_bounds__(256)
agg_kernel(const float* __restrict__ b, const float* __restrict__ gm,
           const float* __restrict__ be, const int* __restrict__ batch) {
    int n = blockIdx.x * 8 + (threadIdx.x >> 5);
    if (n >= N_NODES) return;
    int lane = threadIdx.x & 31;
    const float4* hw4 = (const float4*)g_hw;

    float4 acc = hw4[n * 32 + lane];          // self-loop term
    int start = g_rowptr[n], end = g_rowptr[n + 1];

    for (int base = start; base < end; base += 32) {
        int j = base + lane;
        int idx = (j < end) ? g_col[j] : 0;
        int m = end - base; if (m > 32) m = 32;
        for (int k = 0; k < m; k++) {
            int s = __shfl_sync(0xffffffffu, idx, k);
            float4 v = hw4[s * 32 + lane];
            acc.x += v.x; acc.y += v.y; acc.z += v.z; acc.w += v.w;
        }
    }

    float di = g_dinv[n];
    float rs = rsqrtf(1.0f + BN_EPS);
    float4 bb = __ldg((const float4*)b  + lane);
    float4 gg = __ldg((const float4*)gm + lane);
    float4 ee = __ldg((const float4*)be + lane);
    float4 v;
    v.x = fmaxf((acc.x * di + bb.x) * (gg.x * rs) + ee.x, 0.f);
    v.y = fmaxf((acc.y * di + bb.y) * (gg.y * rs) + ee.y, 0.f);
    v.z = fmaxf((acc.z * di + bb.z) * (gg.z * rs) + ee.z, 0.f);
    v.w = fmaxf((acc.w * di + bb.w) * (gg.w * rs) + ee.w, 0.f);

    if (POOL) {
        int g = __ldg(batch + n);
        red4(g_sums + g * HID + lane * 4, v);
    } else {
        *(float4*)(g_h + n * HID + lane * 4) = v;
    }
}

// ------------------------- final projection ---------------------------------
__global__ void final_kernel(const float* __restrict__ Wp, const float* __restrict__ bp,
                             float* __restrict__ out) {
    __shared__ float p[HID];
    int g = blockIdx.x, j = threadIdx.x;
    float invc = 1.0f / fmaxf((float)g_cnti[g], 1.0f);
    for (int c = j; c < HID; c += EMB) p[c] = g_sums[g * HID + c] * invc;
    __syncthreads();
    float acc = __ldg(bp + j);
    #pragma unroll 8
    for (int c = 0; c < HID; c++) acc += p[c] * __ldg(Wp + c * EMB + j);
    out[g * EMB + j] = acc;
}

// ------------------------- launch -------------------------------------------
extern "C" void kernel_launch(void* const* d_in, const int* in_sizes, int n_in,
                              void* d_out, int out_size) {
    const float* x   = (const float*)d_in[0];
    const int*   src = (const int*)  d_in[1];
    const int*   dst = (const int*)  d_in[2];
    const int*   bat = (const int*)  d_in[3];
    const float* W1  = (const float*)d_in[4];
    const float* b1  = (const float*)d_in[5];
    const float* W2  = (const float*)d_in[6];
    const float* b2  = (const float*)d_in[7];
    const float* W3  = (const float*)d_in[8];
    const float* b3  = (const float*)d_in[9];
    const float* g1  = (const float*)d_in[10];
    const float* be1 = (const float*)d_in[11];
    const float* g2  = (const float*)d_in[12];
    const float* be2 = (const float*)d_in[13];
    const float* g3  = (const float*)d_in[14];
    const float* be3 = (const float*)d_in[15];
    const float* Wp  = (const float*)d_in[16];
    const float* bp  = (const float*)d_in[17];
    float* out = (float*)d_out;

    const int SMEM = 2 * HID * HID * (int)sizeof(float);   // 128 KB
    cudaFuncSetAttribute(gemm128_kernel, cudaFuncAttributeMaxDynamicSharedMemorySize, SMEM);

    const int GEMM_BLOCKS = (N_NODES + 127) / 128;
    const int AGG_BLOCKS  = (N_NODES + 7) / 8;

    // CSR build
    zero_kernel <<<(N_NODES + 255) / 256, 256>>>();
    hist_kernel <<<(N_EDGES + 255) / 256, 256>>>(dst, bat);
    part_kernel <<<NB_SCAN, 256>>>(x);
    scanb_kernel<<<1, 256>>>();
    write_kernel<<<NB_SCAN, 256>>>();
    fill_kernel <<<(N_EDGES + 255) / 256, 256>>>(src, dst);

    // layer 1 (fused 5-wide aggregate + 5x128 GEMM + bn/relu)
    layer1_kernel<<<AGG_BLOCKS, 256>>>(W1, b1, g1, be1);

    // layer 2
    gemm128_kernel<<<GEMM_BLOCKS, 512, SMEM>>>(W2);
    agg_kernel<false><<<AGG_BLOCKS, 256>>>(b2, g2, be2, bat);

    // layer 3 (+ fused mean-pool accumulation)
    gemm128_kernel<<<GEMM_BLOCKS, 512, SMEM>>>(W3);
    agg_kernel<true><<<AGG_BLOCKS, 256>>>(b3, g3, be3, bat);

    final_kernel<<<N_GRAPHS, EMB>>>(Wp, bp, out);
}

// round 5
// speedup vs baseline: 1.6539x; 1.0406x over previous
#include <cuda_runtime.h>

#define N_NODES 50000
#define N_EDGES 600000
#define N_GRAPHS 64
#define HID 128
#define EMB 64
#define BN_EPS 1e-5f
#define NB_CSR 196             // ceil(50000/256)
#define XS_STRIDE 8

// ------------------------- scratch (device globals; no allocs) -------------
__device__ float g_dinv[N_NODES];
__device__ float g_xs [N_NODES * XS_STRIDE];
__device__ float g_hw [N_NODES * HID];
__device__ float g_h  [N_NODES * HID];
__device__ float g_sums[N_GRAPHS * HID];
__device__ int   g_cnti[N_GRAPHS];
__device__ int   g_rowcnt[N_NODES];
__device__ int   g_rowptr[N_NODES];     // segment start (unordered placement)
__device__ int   g_cursor[N_NODES];
__device__ int   g_col[N_EDGES];
__device__ int   g_total;

__device__ __forceinline__ void red4(float* p, float4 v) {
    asm volatile("red.global.add.v4.f32 [%0], {%1,%2,%3,%4};"
                 :: "l"(p), "f"(v.x), "f"(v.y), "f"(v.z), "f"(v.w)
                 : "memory");
}

__device__ __forceinline__ void ffma2(unsigned long long& d, unsigned long long a,
                                      unsigned long long b) {
    asm("fma.rn.f32x2 %0, %1, %2, %0;" : "+l"(d) : "l"(a), "l"(b));
}

// ------------------------- CSR build ---------------------------------------
__global__ void zero_kernel() {
    int i = blockIdx.x * blockDim.x + threadIdx.x;
    if (i < N_NODES) g_rowcnt[i] = 0;
    if (i < N_GRAPHS * HID) g_sums[i] = 0.0f;
    if (i < N_GRAPHS) g_cnti[i] = 0;
    if (i == 0) g_total = 0;
}

__global__ void hist_kernel(const int* __restrict__ dst, const int* __restrict__ batch) {
    int t = blockIdx.x * blockDim.x + threadIdx.x;
    if (t < N_EDGES) atomicAdd(&g_rowcnt[dst[t]], 1);
    if (t < N_NODES) atomicAdd(&g_cnti[batch[t]], 1);
}

// dinv + xs + segment offsets via warp-aggregated atomic (placement unordered)
__global__ void offset_kernel(const float* __restrict__ x) {
    int i = blockIdx.x * 256 + threadIdx.x;
    int lane = threadIdx.x & 31;
    int c = (i < N_NODES) ? g_rowcnt[i] : 0;
    if (i < N_NODES) {
        float di = rsqrtf((float)(c + 1));
        g_dinv[i] = di;
        #pragma unroll
        for (int k = 0; k < 5; k++) g_xs[i * XS_STRIDE + k] = __ldg(x + i * 5 + k) * di;
    }
    // warp inclusive scan of c
    int incl = c;
    #pragma unroll
    for (int off = 1; off < 32; off <<= 1) {
        int v = __shfl_up_sync(0xffffffffu, incl, off);
        if (lane >= off) incl += v;
    }
    int tot = __shfl_sync(0xffffffffu, incl, 31);
    int base = 0;
    if (lane == 31) base = atomicAdd(&g_total, tot);
    base = __shfl_sync(0xffffffffu, base, 31);
    if (i < N_NODES) {
        int start = base + incl - c;
        g_rowptr[i] = start;
        g_cursor[i] = start;
    }
}

__global__ void fill_kernel(const int* __restrict__ src, const int* __restrict__ dst) {
    int e = blockIdx.x * blockDim.x + threadIdx.x;
    if (e < N_EDGES) {
        int p = atomicAdd(&g_cursor[dst[e]], 1);
        g_col[p] = src[e];
    }
}

// ------------------------- fused layer 1 ------------------------------------
__global__ void __launch_bounds__(256)
layer1_kernel(const float* __restrict__ W1, const float* __restrict__ b1,
              const float* __restrict__ gm, const float* __restrict__ be) {
    int n = blockIdx.x * 8 + (threadIdx.x >> 5);
    if (n >= N_NODES) return;
    int lane = threadIdx.x & 31;

    float a0 = 0.f, a1 = 0.f, a2 = 0.f, a3 = 0.f, a4 = 0.f;
    int start = g_rowptr[n];
    int end   = start + g_rowcnt[n];
    for (int j = start + lane; j < end; j += 32) {
        int s = g_col[j];
        float4 v = *(const float4*)(g_xs + s * XS_STRIDE);
        float  w = g_xs[s * XS_STRIDE + 4];
        a0 += v.x; a1 += v.y; a2 += v.z; a3 += v.w; a4 += w;
    }
    #pragma unroll
    for (int off = 16; off > 0; off >>= 1) {
        a0 += __shfl_xor_sync(0xffffffffu, a0, off);
        a1 += __shfl_xor_sync(0xffffffffu, a1, off);
        a2 += __shfl_xor_sync(0xffffffffu, a2, off);
        a3 += __shfl_xor_sync(0xffffffffu, a3, off);
        a4 += __shfl_xor_sync(0xffffffffu, a4, off);
    }
    float4 sv = *(const float4*)(g_xs + n * XS_STRIDE);
    a0 += sv.x; a1 += sv.y; a2 += sv.z; a3 += sv.w; a4 += g_xs[n * XS_STRIDE + 4];

    float di = g_dinv[n];
    float rs = rsqrtf(1.0f + BN_EPS);
    float4 w0 = __ldg((const float4*)(W1 + 0 * HID) + lane);
    float4 w1 = __ldg((const float4*)(W1 + 1 * HID) + lane);
    float4 w2 = __ldg((const float4*)(W1 + 2 * HID) + lane);
    float4 w3 = __ldg((const float4*)(W1 + 3 * HID) + lane);
    float4 w4 = __ldg((const float4*)(W1 + 4 * HID) + lane);
    float4 bb = __ldg((const float4*)b1 + lane);
    float4 gg = __ldg((const float4*)gm + lane);
    float4 ee = __ldg((const float4*)be + lane);

    float4 v;
    v.x = fmaxf(((a0*w0.x + a1*w1.x + a2*w2.x + a3*w3.x + a4*w4.x) * di + bb.x) * (gg.x*rs) + ee.x, 0.f);
    v.y = fmaxf(((a0*w0.y + a1*w1.y + a2*w2.y + a3*w3.y + a4*w4.y) * di + bb.y) * (gg.y*rs) + ee.y, 0.f);
    v.z = fmaxf(((a0*w0.z + a1*w1.z + a2*w2.z + a3*w3.z + a4*w4.z) * di + bb.z) * (gg.z*rs) + ee.z, 0.f);
    v.w = fmaxf(((a0*w0.w + a1*w1.w + a2*w2.w + a3*w3.w + a4*w4.w) * di + bb.w) * (gg.w*rs) + ee.w, 0.f);
    *(float4*)(g_h + n * HID + lane * 4) = v;
}

// ------------------------- 128x128 GEMM via fma.rn.f32x2 --------------------
// Accumulator packs (even-k, odd-k) partial sums. A pair = contiguous LDS.64
// broadcast; B pre-packed (W[2k2][c], W[2k2+1][c]) at word
// k2*256 + (c&3)*64 + (c>>2)*2  (conflict-free LDS.64 for fixed c&3).
__global__ void __launch_bounds__(512, 1)
gemm128_kernel(const float* __restrict__ W) {
    extern __shared__ float smem[];
    float* As = smem;                 // [row][k] row-major, 64KB
    float* Bs = smem + HID * HID;     // packed k-pairs, 64KB
    float4* As4 = (float4*)As;

    int i0 = blockIdx.x * 128;
    int t  = threadIdx.x;

    // load A tile (row-major float4) and pack B
    #pragma unroll
    for (int it = 0; it < 8; it++) {
        int idx = it * 512 + t;       // 0..4095 float4s
        int row = idx >> 5;
        int gi  = i0 + row;
        float4 v = make_float4(0.f, 0.f, 0.f, 0.f);
        if (gi < N_NODES) v = *(const float4*)(g_h + gi * HID + (idx & 31) * 4);
        As4[idx] = v;

        // B: float4 = cols 4*(idx&31) .. +3 of row k=idx>>5
        float4 b = __ldg((const float4*)W + idx);
        int k = idx >> 5;
        int c0 = (idx & 31) * 4;
        int kb = (k >> 1) * 256 + (k & 1);
        Bs[kb + ((c0 + 0) & 3) * 64 + ((c0 + 0) >> 2) * 2] = b.x;
        Bs[kb + ((c0 + 1) & 3) * 64 + ((c0 + 1) >> 2) * 2] = b.y;
        Bs[kb + ((c0 + 2) & 3) * 64 + ((c0 + 2) >> 2) * 2] = b.z;
        Bs[kb + ((c0 + 3) & 3) * 64 + ((c0 + 3) >> 2) * 2] = b.w;
    }
    __syncthreads();

    int w = t >> 5, l = t & 31;
    unsigned long long acc[8][4];
    #pragma unroll
    for (int r = 0; r < 8; r++)
        #pragma unroll
        for (int j = 0; j < 4; j++) acc[r][j] = 0ull;

    const float* Arow = As + (w * 8) * HID;
    #pragma unroll 2
    for (int k2 = 0; k2 < 64; k2++) {
        const float* bk = Bs + k2 * 256 + l * 2;
        unsigned long long b0 = *(const unsigned long long*)(bk + 0 * 64);
        unsigned long long b1 = *(const unsigned long long*)(bk + 1 * 64);
        unsigned long long b2 = *(const unsigned long long*)(bk + 2 * 64);
        unsigned long long b3 = *(const unsigned long long*)(bk + 3 * 64);
        #pragma unroll
        for (int r = 0; r < 8; r++) {
            unsigned long long a = *(const unsigned long long*)(Arow + r * HID + 2 * k2);
            ffma2(acc[r][0], a, b0);
            ffma2(acc[r][1], a, b1);
            ffma2(acc[r][2], a, b2);
            ffma2(acc[r][3], a, b3);
        }
    }

    #pragma unroll
    for (int r = 0; r < 8; r++) {
        int gi = i0 + w * 8 + r;
        if (gi < N_NODES) {
            float s = g_dinv[gi];
            float2 p0 = *(float2*)&acc[r][0];
            float2 p1 = *(float2*)&acc[r][1];
            float2 p2 = *(float2*)&acc[r][2];
            float2 p3 = *(float2*)&acc[r][3];
            float4 o = make_float4((p0.x + p0.y) * s, (p1.x + p1.y) * s,
                                   (p2.x + p2.y) * s, (p3.x + p3.y) * s);
            *(float4*)(g_hw + gi * HID + l * 4) = o;
        }
    }
}

// ------------------------- fused gather-aggregate + bn + relu ---------------
template<bool POOL>
__global__ void __launch_bounds__(256)
agg_kernel(const float* __restrict__ b, const float* __restrict__ gm,
           const float* __restrict__ be, const int* __restrict__ batch) {
    int n = blockIdx.x * 8 + (threadIdx.x >> 5);
    if (n >= N_NODES) return;
    int lane = threadIdx.x & 31;
    const float4* hw4 = (const float4*)g_hw;

    float4 acc = hw4[n * 32 + lane];          // self-loop term
    int start = g_rowptr[n];
    int end   = start + g_rowcnt[n];

    for (int base = start; base < end; base += 32) {
        int j = base + lane;
        int idx = (j < end) ? g_col[j] : 0;
        int m = end - base; if (m > 32) m = 32;
        for (int k = 0; k < m; k++) {
            int s = __shfl_sync(0xffffffffu, idx, k);
            float4 v = hw4[s * 32 + lane];
            acc.x += v.x; acc.y += v.y; acc.z += v.z; acc.w += v.w;
        }
    }

    float di = g_dinv[n];
    float rs = rsqrtf(1.0f + BN_EPS);
    float4 bb = __ldg((const float4*)b  + lane);
    float4 gg = __ldg((const float4*)gm + lane);
    float4 ee = __ldg((const float4*)be + lane);
    float4 v;
    v.x = fmaxf((acc.x * di + bb.x) * (gg.x * rs) + ee.x, 0.f);
    v.y = fmaxf((acc.y * di + bb.y) * (gg.y * rs) + ee.y, 0.f);
    v.z = fmaxf((acc.z * di + bb.z) * (gg.z * rs) + ee.z, 0.f);
    v.w = fmaxf((acc.w * di + bb.w) * (gg.w * rs) + ee.w, 0.f);

    if (POOL) {
        int g = __ldg(batch + n);
        red4(g_sums + g * HID + lane * 4, v);
    } else {
        *(float4*)(g_h + n * HID + lane * 4) = v;
    }
}

// ------------------------- final projection ---------------------------------
__global__ void final_kernel(const float* __restrict__ Wp, const float* __restrict__ bp,
                             float* __restrict__ out) {
    __shared__ float p[HID];
    int g = blockIdx.x, j = threadIdx.x;
    float invc = 1.0f / fmaxf((float)g_cnti[g], 1.0f);
    for (int c = j; c < HID; c += EMB) p[c] = g_sums[g * HID + c] * invc;
    __syncthreads();
    float acc = __ldg(bp + j);
    #pragma unroll 8
    for (int c = 0; c < HID; c++) acc += p[c] * __ldg(Wp + c * EMB + j);
    out[g * EMB + j] = acc;
}

// ------------------------- launch -------------------------------------------
extern "C" void kernel_launch(void* const* d_in, const int* in_sizes, int n_in,
                              void* d_out, int out_size) {
    const float* x   = (const float*)d_in[0];
    const int*   src = (const int*)  d_in[1];
    const int*   dst = (const int*)  d_in[2];
    const int*   bat = (const int*)  d_in[3];
    const float* W1  = (const float*)d_in[4];
    const float* b1  = (const float*)d_in[5];
    const float* W2  = (const float*)d_in[6];
    const float* b2  = (const float*)d_in[7];
    const float* W3  = (const float*)d_in[8];
    const float* b3  = (const float*)d_in[9];
    const float* g1  = (const float*)d_in[10];
    const float* be1 = (const float*)d_in[11];
    const float* g2  = (const float*)d_in[12];
    const float* be2 = (const float*)d_in[13];
    const float* g3  = (const float*)d_in[14];
    const float* be3 = (const float*)d_in[15];
    const float* Wp  = (const float*)d_in[16];
    const float* bp  = (const float*)d_in[17];
    float* out = (float*)d_out;

    const int SMEM = 2 * HID * HID * (int)sizeof(float);   // 128 KB
    cudaFuncSetAttribute(gemm128_kernel, cudaFuncAttributeMaxDynamicSharedMemorySize, SMEM);

    const int GEMM_BLOCKS = (N_NODES + 127) / 128;
    const int AGG_BLOCKS  = (N_NODES + 7) / 8;

    // CSR build (4 kernels)
    zero_kernel  <<<(N_NODES + 255) / 256, 256>>>();
    hist_kernel  <<<(N_EDGES + 255) / 256, 256>>>(dst, bat);
    offset_kernel<<<NB_CSR, 256>>>(x);
    fill_kernel  <<<(N_EDGES + 255) / 256, 256>>>(src, dst);

    // layer 1
    layer1_kernel<<<AGG_BLOCKS, 256>>>(W1, b1, g1, be1);

    // layer 2
    gemm128_kernel<<<GEMM_BLOCKS, 512, SMEM>>>(W2);
    agg_kernel<false><<<AGG_BLOCKS, 256>>>(b2, g2, be2, bat);

    // layer 3 (+ fused mean-pool accumulation)
    gemm128_kernel<<<GEMM_BLOCKS, 512, SMEM>>>(W3);
    agg_kernel<true><<<AGG_BLOCKS, 256>>>(b3, g3, be3, bat);

    final_kernel<<<N_GRAPHS, EMB>>>(Wp, bp, out);
}

// round 6
// speedup vs baseline: 1.9617x; 1.1861x over previous
#include <cuda_runtime.h>
#include <cuda_fp16.h>

#define N_NODES 50000
#define N_EDGES 600000
#define N_GRAPHS 64
#define HID 128
#define EMB 64
#define BN_EPS 1e-5f
#define NB_CSR 196             // ceil(50000/256)
#define XS_STRIDE 8
#define AST 136                // smem row stride in halfs (conflict-free frags)

// ------------------------- scratch (device globals; no allocs) -------------
__device__ float  g_dinv[N_NODES];
__device__ float  g_xs [N_NODES * XS_STRIDE];
__device__ float  g_hw [N_NODES * HID];       // fp32: (h @ W) * dinv
__device__ __half g_h  [N_NODES * HID];       // fp16 activations
__device__ float  g_sums[N_GRAPHS * HID];
__device__ int    g_cnti[N_GRAPHS];
__device__ int    g_rowcnt[N_NODES];
__device__ int    g_rowptr[N_NODES];
__device__ int    g_cursor[N_NODES];
__device__ int    g_col[N_EDGES];
__device__ int    g_total;

__device__ __forceinline__ void red4(float* p, float4 v) {
    asm volatile("red.global.add.v4.f32 [%0], {%1,%2,%3,%4};"
                 :: "l"(p), "f"(v.x), "f"(v.y), "f"(v.z), "f"(v.w)
                 : "memory");
}

// ------------------------- CSR build ---------------------------------------
__global__ void zero_kernel() {
    int i = blockIdx.x * blockDim.x + threadIdx.x;
    if (i < N_NODES) g_rowcnt[i] = 0;
    if (i < N_GRAPHS * HID) g_sums[i] = 0.0f;
    if (i < N_GRAPHS) g_cnti[i] = 0;
    if (i == 0) g_total = 0;
}

__global__ void hist_kernel(const int* __restrict__ dst, const int* __restrict__ batch) {
    int t = blockIdx.x * blockDim.x + threadIdx.x;
    if (t < N_EDGES) atomicAdd(&g_rowcnt[dst[t]], 1);
    if (t < N_NODES) atomicAdd(&g_cnti[batch[t]], 1);
}

__global__ void offset_kernel(const float* __restrict__ x) {
    int i = blockIdx.x * 256 + threadIdx.x;
    int lane = threadIdx.x & 31;
    int c = (i < N_NODES) ? g_rowcnt[i] : 0;
    if (i < N_NODES) {
        float di = rsqrtf((float)(c + 1));
        g_dinv[i] = di;
        #pragma unroll
        for (int k = 0; k < 5; k++) g_xs[i * XS_STRIDE + k] = __ldg(x + i * 5 + k) * di;
    }
    int incl = c;
    #pragma unroll
    for (int off = 1; off < 32; off <<= 1) {
        int v = __shfl_up_sync(0xffffffffu, incl, off);
        if (lane >= off) incl += v;
    }
    int tot = __shfl_sync(0xffffffffu, incl, 31);
    int base = 0;
    if (lane == 31) base = atomicAdd(&g_total, tot);
    base = __shfl_sync(0xffffffffu, base, 31);
    if (i < N_NODES) {
        int start = base + incl - c;
        g_rowptr[i] = start;
        g_cursor[i] = start;
    }
}

__global__ void fill_kernel(const int* __restrict__ src, const int* __restrict__ dst) {
    int e = blockIdx.x * blockDim.x + threadIdx.x;
    if (e < N_EDGES) {
        int p = atomicAdd(&g_cursor[dst[e]], 1);
        g_col[p] = src[e];
    }
}

// ------------------------- fused layer 1 ------------------------------------
__global__ void __launch_bounds__(256)
layer1_kernel(const float* __restrict__ W1, const float* __restrict__ b1,
              const float* __restrict__ gm, const float* __restrict__ be) {
    int n = blockIdx.x * 8 + (threadIdx.x >> 5);
    if (n >= N_NODES) return;
    int lane = threadIdx.x & 31;

    float a0 = 0.f, a1 = 0.f, a2 = 0.f, a3 = 0.f, a4 = 0.f;
    int start = g_rowptr[n];
    int end   = start + g_rowcnt[n];
    for (int j = start + lane; j < end; j += 32) {
        int s = g_col[j];
        float4 v = *(const float4*)(g_xs + s * XS_STRIDE);
        float  w = g_xs[s * XS_STRIDE + 4];
        a0 += v.x; a1 += v.y; a2 += v.z; a3 += v.w; a4 += w;
    }
    #pragma unroll
    for (int off = 16; off > 0; off >>= 1) {
        a0 += __shfl_xor_sync(0xffffffffu, a0, off);
        a1 += __shfl_xor_sync(0xffffffffu, a1, off);
        a2 += __shfl_xor_sync(0xffffffffu, a2, off);
        a3 += __shfl_xor_sync(0xffffffffu, a3, off);
        a4 += __shfl_xor_sync(0xffffffffu, a4, off);
    }
    float4 sv = *(const float4*)(g_xs + n * XS_STRIDE);
    a0 += sv.x; a1 += sv.y; a2 += sv.z; a3 += sv.w; a4 += g_xs[n * XS_STRIDE + 4];

    float di = g_dinv[n];
    float rs = rsqrtf(1.0f + BN_EPS);
    float4 w0 = __ldg((const float4*)(W1 + 0 * HID) + lane);
    float4 w1 = __ldg((const float4*)(W1 + 1 * HID) + lane);
    float4 w2 = __ldg((const float4*)(W1 + 2 * HID) + lane);
    float4 w3 = __ldg((const float4*)(W1 + 3 * HID) + lane);
    float4 w4 = __ldg((const float4*)(W1 + 4 * HID) + lane);
    float4 bb = __ldg((const float4*)b1 + lane);
    float4 gg = __ldg((const float4*)gm + lane);
    float4 ee = __ldg((const float4*)be + lane);

    float4 v;
    v.x = fmaxf(((a0*w0.x + a1*w1.x + a2*w2.x + a3*w3.x + a4*w4.x) * di + bb.x) * (gg.x*rs) + ee.x, 0.f);
    v.y = fmaxf(((a0*w0.y + a1*w1.y + a2*w2.y + a3*w3.y + a4*w4.y) * di + bb.y) * (gg.y*rs) + ee.y, 0.f);
    v.z = fmaxf(((a0*w0.z + a1*w1.z + a2*w2.z + a3*w3.z + a4*w4.z) * di + bb.z) * (gg.z*rs) + ee.z, 0.f);
    v.w = fmaxf(((a0*w0.w + a1*w1.w + a2*w2.w + a3*w3.w + a4*w4.w) * di + bb.w) * (gg.w*rs) + ee.w, 0.f);

    __half2 h01 = __floats2half2_rn(v.x, v.y);
    __half2 h23 = __floats2half2_rn(v.z, v.w);
    uint2 u = make_uint2(*(unsigned*)&h01, *(unsigned*)&h23);
    *(uint2*)(g_h + n * HID + lane * 4) = u;
}

// ------------------------- HMMA 128x128 GEMM (layers 2/3) -------------------
// C[i0:i0+128][0:128] = A(g_h fp16) @ W(fp16) ; epilogue *dinv -> g_hw fp32.
// 512 threads = 16 warps: warp w -> rows (w&7)*16, cols (w>>3)*64.
// mma.sync m16n8k16 row.col: Bt[n][k] in smem (transposed W).
__global__ void __launch_bounds__(512, 1)
gemm128_kernel(const float* __restrict__ W) {
    extern __shared__ __half smem_h[];
    __half* As = smem_h;               // 128 x AST
    __half* Bs = smem_h + 128 * AST;   // 128(n) x AST(k)

    int i0 = blockIdx.x * 128;
    int t  = threadIdx.x;

    // load A tile (fp16, uint4 = 8 halfs)
    #pragma unroll
    for (int it = 0; it < 4; it++) {
        int idx = it * 512 + t;            // 0..2047
        int row = idx >> 4, seg = idx & 15;
        int gi  = i0 + row;
        uint4 v = make_uint4(0u, 0u, 0u, 0u);
        if (gi < N_NODES) v = *(const uint4*)(g_h + gi * HID + seg * 8);
        *(uint4*)(As + row * AST + seg * 8) = v;
    }
    // transpose + convert W -> Bs[n][k]
    #pragma unroll
    for (int it = 0; it < 8; it++) {
        int idx = it * 512 + t;            // 0..4095 float4s
        float4 w = __ldg((const float4*)W + idx);
        int k = idx >> 5, n0 = (idx & 31) * 4;
        Bs[(n0 + 0) * AST + k] = __float2half_rn(w.x);
        Bs[(n0 + 1) * AST + k] = __float2half_rn(w.y);
        Bs[(n0 + 2) * AST + k] = __float2half_rn(w.z);
        Bs[(n0 + 3) * AST + k] = __float2half_rn(w.w);
    }
    __syncthreads();

    int w = t >> 5, lane = t & 31;
    int r0 = (w & 7) * 16;
    int nb = (w >> 3) * 64;
    int g = lane >> 2, tq = lane & 3;

    float acc[8][4];
    #pragma unroll
    for (int nt = 0; nt < 8; nt++)
        #pragma unroll
        for (int j = 0; j < 4; j++) acc[nt][j] = 0.f;

    const __half* Ar0 = As + (r0 + g) * AST;
    const __half* Ar1 = As + (r0 + g + 8) * AST;

    #pragma unroll
    for (int ks = 0; ks < 8; ks++) {
        int k0 = ks * 16;
        unsigned a0 = *(const unsigned*)(Ar0 + k0 + 2 * tq);
        unsigned a1 = *(const unsigned*)(Ar1 + k0 + 2 * tq);
        unsigned a2 = *(const unsigned*)(Ar0 + k0 + 8 + 2 * tq);
        unsigned a3 = *(const unsigned*)(Ar1 + k0 + 8 + 2 * tq);
        #pragma unroll
        for (int nt = 0; nt < 8; nt++) {
            const __half* Bn = Bs + (nb + nt * 8 + g) * AST;
            unsigned b0 = *(const unsigned*)(Bn + k0 + 2 * tq);
            unsigned b1 = *(const unsigned*)(Bn + k0 + 8 + 2 * tq);
            asm volatile(
                "mma.sync.aligned.m16n8k16.row.col.f32.f16.f16.f32 "
                "{%0,%1,%2,%3}, {%4,%5,%6,%7}, {%8,%9}, {%0,%1,%2,%3};"
                : "+f"(acc[nt][0]), "+f"(acc[nt][1]), "+f"(acc[nt][2]), "+f"(acc[nt][3])
                : "r"(a0), "r"(a1), "r"(a2), "r"(a3), "r"(b0), "r"(b1));
        }
    }

    // epilogue: *dinv, store fp32 to g_hw
    int gr1 = i0 + r0 + g;
    int gr2 = gr1 + 8;
    float s1 = (gr1 < N_NODES) ? g_dinv[gr1] : 0.f;
    float s2 = (gr2 < N_NODES) ? g_dinv[gr2] : 0.f;
    #pragma unroll
    for (int nt = 0; nt < 8; nt++) {
        int c0 = nb + nt * 8 + 2 * tq;
        if (gr1 < N_NODES)
            *(float2*)(g_hw + gr1 * HID + c0) = make_float2(acc[nt][0] * s1, acc[nt][1] * s1);
        if (gr2 < N_NODES)
            *(float2*)(g_hw + gr2 * HID + c0) = make_float2(acc[nt][2] * s2, acc[nt][3] * s2);
    }
}

// ------------------------- fused gather-aggregate + bn + relu ---------------
template<bool POOL>
__global__ void __launch_bounds__(256)
agg_kernel(const float* __restrict__ b, const float* __restrict__ gm,
           const float* __restrict__ be, const int* __restrict__ batch) {
    int n = blockIdx.x * 8 + (threadIdx.x >> 5);
    if (n >= N_NODES) return;
    int lane = threadIdx.x & 31;
    const float4* hw4 = (const float4*)g_hw;

    float4 acc = hw4[n * 32 + lane];          // self-loop term
    int start = g_rowptr[n];
    int end   = start + g_rowcnt[n];

    for (int base = start; base < end; base += 32) {
        int j = base + lane;
        int idx = (j < end) ? g_col[j] : 0;
        int m = end - base; if (m > 32) m = 32;
        for (int k = 0; k < m; k++) {
            int s = __shfl_sync(0xffffffffu, idx, k);
            float4 v = hw4[s * 32 + lane];
            acc.x += v.x; acc.y += v.y; acc.z += v.z; acc.w += v.w;
        }
    }

    float di = g_dinv[n];
    float rs = rsqrtf(1.0f + BN_EPS);
    float4 bb = __ldg((const float4*)b  + lane);
    float4 gg = __ldg((const float4*)gm + lane);
    float4 ee = __ldg((const float4*)be + lane);
    float4 v;
    v.x = fmaxf((acc.x * di + bb.x) * (gg.x * rs) + ee.x, 0.f);
    v.y = fmaxf((acc.y * di + bb.y) * (gg.y * rs) + ee.y, 0.f);
    v.z = fmaxf((acc.z * di + bb.z) * (gg.z * rs) + ee.z, 0.f);
    v.w = fmaxf((acc.w * di + bb.w) * (gg.w * rs) + ee.w, 0.f);

    if (POOL) {
        int g = __ldg(batch + n);
        red4(g_sums + g * HID + lane * 4, v);
    } else {
        __half2 h01 = __floats2half2_rn(v.x, v.y);
        __half2 h23 = __floats2half2_rn(v.z, v.w);
        uint2 u = make_uint2(*(unsigned*)&h01, *(unsigned*)&h23);
        *(uint2*)(g_h + n * HID + lane * 4) = u;
    }
}

// ------------------------- final projection ---------------------------------
__global__ void final_kernel(const float* __restrict__ Wp, const float* __restrict__ bp,
                             float* __restrict__ out) {
    __shared__ float p[HID];
    int g = blockIdx.x, j = threadIdx.x;
    float invc = 1.0f / fmaxf((float)g_cnti[g], 1.0f);
    for (int c = j; c < HID; c += EMB) p[c] = g_sums[g * HID + c] * invc;
    __syncthreads();
    float acc = __ldg(bp + j);
    #pragma unroll 8
    for (int c = 0; c < HID; c++) acc += p[c] * __ldg(Wp + c * EMB + j);
    out[g * EMB + j] = acc;
}

// ------------------------- launch -------------------------------------------
extern "C" void kernel_launch(void* const* d_in, const int* in_sizes, int n_in,
                              void* d_out, int out_size) {
    const float* x   = (const float*)d_in[0];
    const int*   src = (const int*)  d_in[1];
    const int*   dst = (const int*)  d_in[2];
    const int*   bat = (const int*)  d_in[3];
    const float* W1  = (const float*)d_in[4];
    const float* b1  = (const float*)d_in[5];
    const float* W2  = (const float*)d_in[6];
    const float* b2  = (const float*)d_in[7];
    const float* W3  = (const float*)d_in[8];
    const float* b3  = (const float*)d_in[9];
    const float* g1  = (const float*)d_in[10];
    const float* be1 = (const float*)d_in[11];
    const float* g2  = (const float*)d_in[12];
    const float* be2 = (const float*)d_in[13];
    const float* g3  = (const float*)d_in[14];
    const float* be3 = (const float*)d_in[15];
    const float* Wp  = (const float*)d_in[16];
    const float* bp  = (const float*)d_in[17];
    float* out = (float*)d_out;

    const int SMEM = 2 * 128 * AST * (int)sizeof(__half);   // ~68 KB
    cudaFuncSetAttribute(gemm128_kernel, cudaFuncAttributeMaxDynamicSharedMemorySize, SMEM);

    const int GEMM_BLOCKS = (N_NODES + 127) / 128;
    const int AGG_BLOCKS  = (N_NODES + 7) / 8;

    // CSR build
    zero_kernel  <<<(N_NODES + 255) / 256, 256>>>();
    hist_kernel  <<<(N_EDGES + 255) / 256, 256>>>(dst, bat);
    offset_kernel<<<NB_CSR, 256>>>(x);
    fill_kernel  <<<(N_EDGES + 255) / 256, 256>>>(src, dst);

    // layer 1
    layer1_kernel<<<AGG_BLOCKS, 256>>>(W1, b1, g1, be1);

    // layer 2
    gemm128_kernel<<<GEMM_BLOCKS, 512, SMEM>>>(W2);
    agg_kernel<false><<<AGG_BLOCKS, 256>>>(b2, g2, be2, bat);

    // layer 3 (+ fused mean-pool accumulation)
    gemm128_kernel<<<GEMM_BLOCKS, 512, SMEM>>>(W3);
    agg_kernel<true><<<AGG_BLOCKS, 256>>>(b3, g3, be3, bat);

    final_kernel<<<N_GRAPHS, EMB>>>(Wp, bp, out);
}

// round 7
// speedup vs baseline: 2.4564x; 1.2522x over previous
#include <cuda_runtime.h>
#include <cuda_fp16.h>

#define N_NODES 50000
#define N_EDGES 600000
#define N_GRAPHS 64
#define HID 128
#define EMB 64
#define BN_EPS 1e-5f
#define NB_CSR 196             // ceil(50000/256)
#define XS_STRIDE 8
#define AST 136                // smem row stride in halfs (conflict-free frags)

// ------------------------- scratch (device globals; no allocs) -------------
__device__ float  g_dinv[N_NODES];
__device__ float  g_xs [N_NODES * XS_STRIDE];
__device__ float  g_hw [N_NODES * HID];       // fp32: (h @ W) * dinv
__device__ __half g_h  [N_NODES * HID];       // fp16 activations
__device__ __half g_Wt2[HID * HID];           // W2^T fp16 [n][k]
__device__ __half g_Wt3[HID * HID];           // W3^T fp16 [n][k]
__device__ float  g_sums[N_GRAPHS * HID];
__device__ int    g_cnti[N_GRAPHS];
__device__ int    g_rowcnt[N_NODES];
__device__ int    g_rowptr[N_NODES];
__device__ int    g_cursor[N_NODES];
__device__ int    g_col[N_EDGES];
__device__ int    g_total;

__device__ __forceinline__ void red4(float* p, float4 v) {
    asm volatile("red.global.add.v4.f32 [%0], {%1,%2,%3,%4};"
                 :: "l"(p), "f"(v.x), "f"(v.y), "f"(v.z), "f"(v.w)
                 : "memory");
}

__device__ __forceinline__ void add2(unsigned long long& d, unsigned long long a) {
    asm("add.rn.f32x2 %0, %0, %1;" : "+l"(d) : "l"(a));
}

// ------------------------- CSR build ---------------------------------------
__global__ void zero_kernel() {
    int i = blockIdx.x * blockDim.x + threadIdx.x;
    if (i < N_NODES) g_rowcnt[i] = 0;
    if (i < N_GRAPHS * HID) g_sums[i] = 0.0f;
    if (i < N_GRAPHS) g_cnti[i] = 0;
    if (i == 0) g_total = 0;
}

__global__ void hist_kernel(const int* __restrict__ dst, const int* __restrict__ batch) {
    int t = blockIdx.x * blockDim.x + threadIdx.x;
    if (t < N_EDGES) atomicAdd(&g_rowcnt[dst[t]], 1);
    if (t < N_NODES) {
        int g = batch[t];
        unsigned act = __activemask();
        unsigned m = __match_any_sync(act, g);
        int leader = __ffs(m) - 1;
        if ((int)(threadIdx.x & 31) == leader) atomicAdd(&g_cnti[g], __popc(m));
    }
}

// W2/W3 -> fp16 transposed [n][k]
__global__ void wt_kernel(const float* __restrict__ W2, const float* __restrict__ W3) {
    int idx = blockIdx.x * 256 + threadIdx.x;   // 0..16383
    int k = idx >> 7, n = idx & 127;
    g_Wt2[n * HID + k] = __float2half_rn(W2[idx]);
    g_Wt3[n * HID + k] = __float2half_rn(W3[idx]);
}

__global__ void offset_kernel(const float* __restrict__ x) {
    int i = blockIdx.x * 256 + threadIdx.x;
    int lane = threadIdx.x & 31;
    int c = (i < N_NODES) ? g_rowcnt[i] : 0;
    if (i < N_NODES) {
        float di = rsqrtf((float)(c + 1));
        g_dinv[i] = di;
        #pragma unroll
        for (int k = 0; k < 5; k++) g_xs[i * XS_STRIDE + k] = __ldg(x + i * 5 + k) * di;
    }
    int incl = c;
    #pragma unroll
    for (int off = 1; off < 32; off <<= 1) {
        int v = __shfl_up_sync(0xffffffffu, incl, off);
        if (lane >= off) incl += v;
    }
    int tot = __shfl_sync(0xffffffffu, incl, 31);
    int base = 0;
    if (lane == 31) base = atomicAdd(&g_total, tot);
    base = __shfl_sync(0xffffffffu, base, 31);
    if (i < N_NODES) {
        int start = base + incl - c;
        g_rowptr[i] = start;
        g_cursor[i] = start;
    }
}

__global__ void fill_kernel(const int* __restrict__ src, const int* __restrict__ dst) {
    int e = blockIdx.x * blockDim.x + threadIdx.x;
    if (e < N_EDGES) {
        int p = atomicAdd(&g_cursor[dst[e]], 1);
        g_col[p] = src[e];
    }
}

// ------------------------- fused layer 1 ------------------------------------
__global__ void __launch_bounds__(256)
layer1_kernel(const float* __restrict__ W1, const float* __restrict__ b1,
              const float* __restrict__ gm, const float* __restrict__ be) {
    int n = blockIdx.x * 8 + (threadIdx.x >> 5);
    if (n >= N_NODES) return;
    int lane = threadIdx.x & 31;

    float a0 = 0.f, a1 = 0.f, a2 = 0.f, a3 = 0.f, a4 = 0.f;
    int start = g_rowptr[n];
    int end   = start + g_rowcnt[n];
    for (int j = start + lane; j < end; j += 32) {
        int s = g_col[j];
        float4 v = *(const float4*)(g_xs + s * XS_STRIDE);
        float  w = g_xs[s * XS_STRIDE + 4];
        a0 += v.x; a1 += v.y; a2 += v.z; a3 += v.w; a4 += w;
    }
    #pragma unroll
    for (int off = 16; off > 0; off >>= 1) {
        a0 += __shfl_xor_sync(0xffffffffu, a0, off);
        a1 += __shfl_xor_sync(0xffffffffu, a1, off);
        a2 += __shfl_xor_sync(0xffffffffu, a2, off);
        a3 += __shfl_xor_sync(0xffffffffu, a3, off);
        a4 += __shfl_xor_sync(0xffffffffu, a4, off);
    }
    float4 sv = *(const float4*)(g_xs + n * XS_STRIDE);
    a0 += sv.x; a1 += sv.y; a2 += sv.z; a3 += sv.w; a4 += g_xs[n * XS_STRIDE + 4];

    float di = g_dinv[n];
    float rs = rsqrtf(1.0f + BN_EPS);
    float4 w0 = __ldg((const float4*)(W1 + 0 * HID) + lane);
    float4 w1 = __ldg((const float4*)(W1 + 1 * HID) + lane);
    float4 w2 = __ldg((const float4*)(W1 + 2 * HID) + lane);
    float4 w3 = __ldg((const float4*)(W1 + 3 * HID) + lane);
    float4 w4 = __ldg((const float4*)(W1 + 4 * HID) + lane);
    float4 bb = __ldg((const float4*)b1 + lane);
    float4 gg = __ldg((const float4*)gm + lane);
    float4 ee = __ldg((const float4*)be + lane);

    float4 v;
    v.x = fmaxf(((a0*w0.x + a1*w1.x + a2*w2.x + a3*w3.x + a4*w4.x) * di + bb.x) * (gg.x*rs) + ee.x, 0.f);
    v.y = fmaxf(((a0*w0.y + a1*w1.y + a2*w2.y + a3*w3.y + a4*w4.y) * di + bb.y) * (gg.y*rs) + ee.y, 0.f);
    v.z = fmaxf(((a0*w0.z + a1*w1.z + a2*w2.z + a3*w3.z + a4*w4.z) * di + bb.z) * (gg.z*rs) + ee.z, 0.f);
    v.w = fmaxf(((a0*w0.w + a1*w1.w + a2*w2.w + a3*w3.w + a4*w4.w) * di + bb.w) * (gg.w*rs) + ee.w, 0.f);

    __half2 h01 = __floats2half2_rn(v.x, v.y);
    __half2 h23 = __floats2half2_rn(v.z, v.w);
    uint2 u = make_uint2(*(unsigned*)&h01, *(unsigned*)&h23);
    *(uint2*)(g_h + n * HID + lane * 4) = u;
}

// ------------------------- HMMA 128x128 GEMM (layers 2/3) -------------------
// A = g_h (fp16), B = precomputed Wt fp16 [n][k]. Epilogue *dinv -> g_hw fp32.
__global__ void __launch_bounds__(512, 1)
gemm128_kernel(const __half* __restrict__ Wt) {
    extern __shared__ __half smem_h[];
    __half* As = smem_h;               // 128 x AST
    __half* Bs = smem_h + 128 * AST;   // 128(n) x AST(k)

    int i0 = blockIdx.x * 128;
    int t  = threadIdx.x;

    // load A tile + B tile (fp16, uint4 = 8 halfs)
    #pragma unroll
    for (int it = 0; it < 4; it++) {
        int idx = it * 512 + t;            // 0..2047
        int row = idx >> 4, seg = idx & 15;
        int gi  = i0 + row;
        uint4 v = make_uint4(0u, 0u, 0u, 0u);
        if (gi < N_NODES) v = *(const uint4*)(g_h + gi * HID + seg * 8);
        *(uint4*)(As + row * AST + seg * 8) = v;

        uint4 b = *(const uint4*)(Wt + row * HID + seg * 8);
        *(uint4*)(Bs + row * AST + seg * 8) = b;
    }
    __syncthreads();

    int w = t >> 5, lane = t & 31;
    int r0 = (w & 7) * 16;
    int nb = (w >> 3) * 64;
    int g = lane >> 2, tq = lane & 3;

    float acc[8][4];
    #pragma unroll
    for (int nt = 0; nt < 8; nt++)
        #pragma unroll
        for (int j = 0; j < 4; j++) acc[nt][j] = 0.f;

    const __half* Ar0 = As + (r0 + g) * AST;
    const __half* Ar1 = As + (r0 + g + 8) * AST;

    #pragma unroll
    for (int ks = 0; ks < 8; ks++) {
        int k0 = ks * 16;
        unsigned a0 = *(const unsigned*)(Ar0 + k0 + 2 * tq);
        unsigned a1 = *(const unsigned*)(Ar1 + k0 + 2 * tq);
        unsigned a2 = *(const unsigned*)(Ar0 + k0 + 8 + 2 * tq);
        unsigned a3 = *(const unsigned*)(Ar1 + k0 + 8 + 2 * tq);
        #pragma unroll
        for (int nt = 0; nt < 8; nt++) {
            const __half* Bn = Bs + (nb + nt * 8 + g) * AST;
            unsigned b0 = *(const unsigned*)(Bn + k0 + 2 * tq);
            unsigned b1 = *(const unsigned*)(Bn + k0 + 8 + 2 * tq);
            asm volatile(
                "mma.sync.aligned.m16n8k16.row.col.f32.f16.f16.f32 "
                "{%0,%1,%2,%3}, {%4,%5,%6,%7}, {%8,%9}, {%0,%1,%2,%3};"
                : "+f"(acc[nt][0]), "+f"(acc[nt][1]), "+f"(acc[nt][2]), "+f"(acc[nt][3])
                : "r"(a0), "r"(a1), "r"(a2), "r"(a3), "r"(b0), "r"(b1));
        }
    }

    int gr1 = i0 + r0 + g;
    int gr2 = gr1 + 8;
    float s1 = (gr1 < N_NODES) ? g_dinv[gr1] : 0.f;
    float s2 = (gr2 < N_NODES) ? g_dinv[gr2] : 0.f;
    #pragma unroll
    for (int nt = 0; nt < 8; nt++) {
        int c0 = nb + nt * 8 + 2 * tq;
        if (gr1 < N_NODES)
            *(float2*)(g_hw + gr1 * HID + c0) = make_float2(acc[nt][0] * s1, acc[nt][1] * s1);
        if (gr2 < N_NODES)
            *(float2*)(g_hw + gr2 * HID + c0) = make_float2(acc[nt][2] * s2, acc[nt][3] * s2);
    }
}

// ------------------------- fused gather-aggregate + bn + relu ---------------
template<bool POOL>
__global__ void __launch_bounds__(256)
agg_kernel(const float* __restrict__ b, const float* __restrict__ gm,
           const float* __restrict__ be, const int* __restrict__ batch) {
    int n = blockIdx.x * 8 + (threadIdx.x >> 5);
    if (n >= N_NODES) return;
    int lane = threadIdx.x & 31;
    const ulonglong2* hw2 = (const ulonglong2*)g_hw;   // 16B = 4 floats

    ulonglong2 self = hw2[n * 32 + lane];
    unsigned long long acc0 = self.x, acc1 = self.y;   // packed f32x2 pairs

    int start = g_rowptr[n];
    int end   = start + g_rowcnt[n];
    for (int base = start; base < end; base += 32) {
        int j = base + lane;
        int idx = (j < end) ? g_col[j] : 0;
        int m = end - base; if (m > 32) m = 32;
        for (int k = 0; k < m; k++) {
            int s = __shfl_sync(0xffffffffu, idx, k);
            ulonglong2 u = hw2[s * 32 + lane];
            add2(acc0, u.x);
            add2(acc1, u.y);
        }
    }

    float2 p01 = *(float2*)&acc0;
    float2 p23 = *(float2*)&acc1;
    float di = g_dinv[n];
    float rs = rsqrtf(1.0f + BN_EPS);
    float4 bb = __ldg((const float4*)b  + lane);
    float4 gg = __ldg((const float4*)gm + lane);
    float4 ee = __ldg((const float4*)be + lane);
    float4 v;
    v.x = fmaxf((p01.x * di + bb.x) * (gg.x * rs) + ee.x, 0.f);
    v.y = fmaxf((p01.y * di + bb.y) * (gg.y * rs) + ee.y, 0.f);
    v.z = fmaxf((p23.x * di + bb.z) * (gg.z * rs) + ee.z, 0.f);
    v.w = fmaxf((p23.y * di + bb.w) * (gg.w * rs) + ee.w, 0.f);

    if (POOL) {
        int g = __ldg(batch + n);
        red4(g_sums + g * HID + lane * 4, v);
    } else {
        __half2 h01 = __floats2half2_rn(v.x, v.y);
        __half2 h23 = __floats2half2_rn(v.z, v.w);
        uint2 u = make_uint2(*(unsigned*)&h01, *(unsigned*)&h23);
        *(uint2*)(g_h + n * HID + lane * 4) = u;
    }
}

// ------------------------- final projection ---------------------------------
__global__ void final_kernel(const float* __restrict__ Wp, const float* __restrict__ bp,
                             float* __restrict__ out) {
    __shared__ float p[HID];
    int g = blockIdx.x, j = threadIdx.x;
    float invc = 1.0f / fmaxf((float)g_cnti[g], 1.0f);
    for (int c = j; c < HID; c += EMB) p[c] = g_sums[g * HID + c] * invc;
    __syncthreads();
    float acc = __ldg(bp + j);
    #pragma unroll 8
    for (int c = 0; c < HID; c++) acc += p[c] * __ldg(Wp + c * EMB + j);
    out[g * EMB + j] = acc;
}

// ------------------------- launch -------------------------------------------
extern "C" void kernel_launch(void* const* d_in, const int* in_sizes, int n_in,
                              void* d_out, int out_size) {
    const float* x   = (const float*)d_in[0];
    const int*   src = (const int*)  d_in[1];
    const int*   dst = (const int*)  d_in[2];
    const int*   bat = (const int*)  d_in[3];
    const float* W1  = (const float*)d_in[4];
    const float* b1  = (const float*)d_in[5];
    const float* W2  = (const float*)d_in[6];
    const float* b2  = (const float*)d_in[7];
    const float* W3  = (const float*)d_in[8];
    const float* b3  = (const float*)d_in[9];
    const float* g1  = (const float*)d_in[10];
    const float* be1 = (const float*)d_in[11];
    const float* g2  = (const float*)d_in[12];
    const float* be2 = (const float*)d_in[13];
    const float* g3  = (const float*)d_in[14];
    const float* be3 = (const float*)d_in[15];
    const float* Wp  = (const float*)d_in[16];
    const float* bp  = (const float*)d_in[17];
    float* out = (float*)d_out;

    const __half* wt2;
    const __half* wt3;
    cudaGetSymbolAddress((void**)&wt2, g_Wt2);
    cudaGetSymbolAddress((void**)&wt3, g_Wt3);

    const int SMEM = 2 * 128 * AST * (int)sizeof(__half);   // ~68 KB
    cudaFuncSetAttribute(gemm128_kernel, cudaFuncAttributeMaxDynamicSharedMemorySize, SMEM);

    const int GEMM_BLOCKS = (N_NODES + 127) / 128;
    const int AGG_BLOCKS  = (N_NODES + 7) / 8;

    // CSR build + weight prep
    zero_kernel  <<<(N_NODES + 255) / 256, 256>>>();
    hist_kernel  <<<(N_EDGES + 255) / 256, 256>>>(dst, bat);
    wt_kernel    <<<64, 256>>>(W2, W3);
    offset_kernel<<<NB_CSR, 256>>>(x);
    fill_kernel  <<<(N_EDGES + 255) / 256, 256>>>(src, dst);

    // layer 1
    layer1_kernel<<<AGG_BLOCKS, 256>>>(W1, b1, g1, be1);

    // layer 2
    gemm128_kernel<<<GEMM_BLOCKS, 512, SMEM>>>(wt2);
    agg_kernel<false><<<AGG_BLOCKS, 256>>>(b2, g2, be2, bat);

    // layer 3 (+ fused mean-pool accumulation)
    gemm128_kernel<<<GEMM_BLOCKS, 512, SMEM>>>(wt3);
    agg_kernel<true><<<AGG_BLOCKS, 256>>>(b3, g3, be3, bat);

    final_kernel<<<N_GRAPHS, EMB>>>(Wp, bp, out);
}